// round 10
// baseline (speedup 1.0000x reference)
#include <cuda_runtime.h>
#include <cuda_bf16.h>
#include <cstdint>
#include <math.h>

// Problem constants
#define BROWS 8192
#define DIM   512
#define INV_T 14.285714285714286f   // 1/0.07

// Tiling: CTA 128x128, warp 32x64, mma m16n8k16 bf16
#define TM 128
#define TN 128
#define KC 64                        // bf16 elements per chunk (128B rows)
#define NCHUNK (DIM / KC)            // 8
#define NB (BROWS / TM)              // 64 blocks per dim
#define NTILES (NB * (NB + 1) / 2)   // 2080 lower-tri tiles
#define GRIDSZ 592                   // 148 SMs x occ 2, x2 safety

#define TILE_BYTES  (128 * 128)      // one 128-row x 128B tile (16 KB)
#define STAGE_BYTES (2 * TILE_BYTES) // A + B (32 KB)
#define STAGES 3
#define SMEM_BYTES  (STAGES * STAGE_BYTES)   // 96 KB

#define SWZ(o) ((o) ^ (((o) >> 3) & 0x70))

// Scratch (static device globals — no allocation)
__device__ __nv_bfloat16 g_f[BROWS * DIM];   // bf16 normalized features (8 MB)
__device__ float g_partial[NB][BROWS];       // per-block exp row sums
__device__ float g_rowval[BROWS];
__device__ unsigned g_ctr;                   // work-stealing tile counter

// ---------------------------------------------------------------------------
__device__ __forceinline__ uint32_t smem_u32(const void* p) {
    uint32_t a;
    asm("{ .reg .u64 t; cvta.to.shared.u64 t, %1; cvt.u32.u64 %0, t; }"
        : "=r"(a) : "l"(p));
    return a;
}
__device__ __forceinline__ void cp16(uint32_t dst, const void* src) {
    asm volatile("cp.async.cg.shared.global [%0], [%1], 16;"
                 :: "r"(dst), "l"(src) : "memory");
}
__device__ __forceinline__ void ldsm_x4(uint32_t* r, uint32_t addr) {
    asm volatile("ldmatrix.sync.aligned.m8n8.x4.shared.b16 {%0,%1,%2,%3}, [%4];"
                 : "=r"(r[0]), "=r"(r[1]), "=r"(r[2]), "=r"(r[3]) : "r"(addr));
}
__device__ __forceinline__ void mma_bf16(float* c, const uint32_t* a,
                                         uint32_t b0, uint32_t b1) {
    asm volatile(
        "mma.sync.aligned.m16n8k16.row.col.f32.bf16.bf16.f32 "
        "{%0,%1,%2,%3}, {%4,%5,%6,%7}, {%8,%9}, {%0,%1,%2,%3};"
        : "+f"(c[0]), "+f"(c[1]), "+f"(c[2]), "+f"(c[3])
        : "r"(a[0]), "r"(a[1]), "r"(a[2]), "r"(a[3]), "r"(b0), "r"(b1));
}

// ---------------------------------------------------------------------------
// Kernel A: row L2-normalize + round to bf16; also resets the tile counter.
// ---------------------------------------------------------------------------
__global__ void normalize_kernel(const float* __restrict__ x) {
    if (blockIdx.x == 0 && threadIdx.x == 0 && threadIdx.y == 0) g_ctr = 0;
    int row  = blockIdx.x * 8 + threadIdx.y;
    int lane = threadIdx.x;
    const float* xr = x + (size_t)row * DIM;
    float v[16];
    float s = 0.f;
#pragma unroll
    for (int i = 0; i < 16; i++) { v[i] = xr[lane + i * 32]; s += v[i] * v[i]; }
#pragma unroll
    for (int o = 16; o; o >>= 1) s += __shfl_xor_sync(0xffffffffu, s, o);
    float inv = 1.0f / fmaxf(sqrtf(s), 1e-12f);
    __nv_bfloat16* fr = g_f + (size_t)row * DIM;
#pragma unroll
    for (int i = 0; i < 16; i++)
        fr[lane + i * 32] = __float2bfloat16_rn(v[i] * inv);
}

// ---------------------------------------------------------------------------
// Kernel B: persistent work-stealing bf16 mma.sync GEMM over lower-tri tiles.
// Per-tile schedule = R6 (fastest measured). Tile->CTA assignment via atomic
// counter is nondeterministic, but each tile writes fixed g_partial slots
// (single writer) so the output is bitwise deterministic.
// ---------------------------------------------------------------------------
extern __shared__ char dynsm[];

__global__ __launch_bounds__(256, 2) void gemm_lse_mma() {
    __shared__ float red_r[TM][2];
    __shared__ float red_c[TN][4];
    __shared__ unsigned tile_idx_sh;

    const int tid  = threadIdx.x;
    const int wid  = tid >> 5;
    const int lane = tid & 31;
    const int wr   = wid & 3;
    const int wc   = wid >> 2;
    const int g    = lane >> 2;
    const int t    = lane & 3;

    const uint32_t smem_base = smem_u32(dynsm);
    const int srow = tid >> 3;
    const int sseg = tid & 7;

    const int a_row  = wr * 32 + (lane & 15);
    const int a_koff = (lane >> 4) * 16;
    const int b_row  = wc * 64 + (lane & 7) + ((lane >> 4) << 3);
    const int b_koff = ((lane >> 3) & 1) * 16;

    while (true) {
        // ---- grab next tile ----
        if (tid == 0) tile_idx_sh = atomicAdd(&g_ctr, 1u);
        __syncthreads();
        const unsigned idx = tile_idx_sh;
        __syncthreads();
        if (idx >= NTILES) break;

        // decode lower-tri pair (bi >= bj)
        int bi = (int)((sqrtf(8.0f * (float)idx + 1.0f) - 1.0f) * 0.5f);
        while ((bi + 1) * (bi + 2) / 2 <= (int)idx) bi++;
        while (bi * (bi + 1) / 2 > (int)idx) bi--;
        int bj = (int)idx - bi * (bi + 1) / 2;
        const int r0 = bi * TM;
        const int j0 = bj * TN;
        const bool offdiag = (bi != bj);

        const __nv_bfloat16* srcA = g_f + (size_t)r0 * DIM;
        const __nv_bfloat16* srcB = g_f + (size_t)j0 * DIM;

        float acc[2][8][4];
#pragma unroll
        for (int mt = 0; mt < 2; mt++)
#pragma unroll
            for (int nt = 0; nt < 8; nt++)
#pragma unroll
                for (int rr = 0; rr < 4; rr++) acc[mt][nt][rr] = 0.f;

        auto issue_chunk = [&](int c, int s) {
            const uint32_t sa = smem_base + s * STAGE_BYTES;
            const int ko = c * KC;
#pragma unroll
            for (int it = 0; it < 4; it++) {
                int row = srow + it * 32;
                uint32_t off = SWZ(row * 128 + sseg * 16);
                cp16(sa + off, srcA + (size_t)row * DIM + ko + sseg * 8);
                cp16(sa + TILE_BYTES + off, srcB + (size_t)row * DIM + ko + sseg * 8);
            }
            asm volatile("cp.async.commit_group;" ::: "memory");
        };

        // prologue: stages 0..STAGES-2
#pragma unroll
        for (int s = 0; s < STAGES - 1; s++) issue_chunk(s, s);

        for (int c = 0; c < NCHUNK; c++) {
            if (c + STAGES - 1 < NCHUNK) {
                issue_chunk(c + STAGES - 1, (c + STAGES - 1) % STAGES);
                asm volatile("cp.async.wait_group %0;" :: "n"(STAGES - 2) : "memory");
            } else {
                asm volatile("cp.async.wait_group 0;" ::: "memory");
            }
            __syncthreads();

            const uint32_t sa = smem_base + (c % STAGES) * STAGE_BYTES;
            const uint32_t sb = sa + TILE_BYTES;

#pragma unroll
            for (int kstep = 0; kstep < 4; kstep++) {
                uint32_t afr[2][4];
#pragma unroll
                for (int mt = 0; mt < 2; mt++) {
                    int off = SWZ((a_row + mt * 16) * 128 + kstep * 32 + a_koff);
                    ldsm_x4(afr[mt], sa + off);
                }
                uint32_t bfr[8][2];
#pragma unroll
                for (int p = 0; p < 4; p++) {
                    uint32_t r[4];
                    int off = SWZ((b_row + p * 16) * 128 + kstep * 32 + b_koff);
                    ldsm_x4(r, sb + off);
                    bfr[2 * p][0] = r[0]; bfr[2 * p][1] = r[1];
                    bfr[2 * p + 1][0] = r[2]; bfr[2 * p + 1][1] = r[3];
                }
#pragma unroll
                for (int mt = 0; mt < 2; mt++)
#pragma unroll
                    for (int nt = 0; nt < 8; nt++)
                        mma_bf16(acc[mt][nt], afr[mt], bfr[nt][0], bfr[nt][1]);
            }
            __syncthreads();   // all reads of this stage done before reuse
        }

        // ---- epilogue: exp in place; row sums + col sums (off-diag) ----
#pragma unroll
        for (int mt = 0; mt < 2; mt++)
#pragma unroll
            for (int nt = 0; nt < 8; nt++)
#pragma unroll
                for (int rr = 0; rr < 4; rr++)
                    acc[mt][nt][rr] = __expf((acc[mt][nt][rr] - 1.0f) * INV_T);

#pragma unroll
        for (int mt = 0; mt < 2; mt++)
#pragma unroll
            for (int hi = 0; hi < 2; hi++) {
                float s = 0.f;
#pragma unroll
                for (int nt = 0; nt < 8; nt++)
                    s += acc[mt][nt][hi * 2 + 0] + acc[mt][nt][hi * 2 + 1];
                s += __shfl_xor_sync(0xffffffffu, s, 1);
                s += __shfl_xor_sync(0xffffffffu, s, 2);
                if (t == 0) red_r[wr * 32 + mt * 16 + hi * 8 + g][wc] = s;
            }

        if (offdiag) {
#pragma unroll
            for (int nt = 0; nt < 8; nt++) {
                float cs0 = acc[0][nt][0] + acc[0][nt][2] + acc[1][nt][0] + acc[1][nt][2];
                float cs1 = acc[0][nt][1] + acc[0][nt][3] + acc[1][nt][1] + acc[1][nt][3];
#pragma unroll
                for (int o = 4; o <= 16; o <<= 1) {
                    cs0 += __shfl_xor_sync(0xffffffffu, cs0, o);
                    cs1 += __shfl_xor_sync(0xffffffffu, cs1, o);
                }
                if (g == 0) {
                    red_c[wc * 64 + nt * 8 + t * 2 + 0][wr] = cs0;
                    red_c[wc * 64 + nt * 8 + t * 2 + 1][wr] = cs1;
                }
            }
        }
        __syncthreads();

        if (tid < TM) {
            g_partial[bj][r0 + tid] = red_r[tid][0] + red_r[tid][1];
            if (offdiag)
                g_partial[bi][j0 + tid] =
                    red_c[tid][0] + red_c[tid][1] + red_c[tid][2] + red_c[tid][3];
        }
        __syncthreads();   // red_* reuse safety for next tile
    }
}

// ---------------------------------------------------------------------------
// Kernel C: labels (col 0/1), picked dot (bf16 inputs, fp32 accum), lse
// ---------------------------------------------------------------------------
__global__ void pick_kernel(const int* __restrict__ ids,
                            const int* __restrict__ anchor) {
    int row  = blockIdx.x * 8 + threadIdx.y;
    int lane = threadIdx.x;

    int aid       = ids[anchor[0]];
    int same_last = (ids[BROWS - 1] == aid);
    int label;
    if (row == BROWS - 1)
        label = (same_last && (ids[BROWS - 2] == aid)) ? 1 : 0;
    else
        label = ((ids[row] == aid) && same_last) ? 1 : 0;

    const __nv_bfloat16* fi = g_f + (size_t)row * DIM;
    const __nv_bfloat16* fc = g_f + (size_t)label * DIM;
    float d = 0.f;
#pragma unroll
    for (int i = 0; i < 16; i++)
        d = fmaf(__bfloat162float(fi[lane + i * 32]),
                 __bfloat162float(fc[lane + i * 32]), d);

    // parallel partial-slot sum: lanes each grab 2 of the 64 slots
    float rs = g_partial[lane][row] + g_partial[lane + 32][row];

#pragma unroll
    for (int o = 16; o; o >>= 1) {
        d  += __shfl_xor_sync(0xffffffffu, d, o);
        rs += __shfl_xor_sync(0xffffffffu, rs, o);
    }

    if (lane == 0) {
        float lse = INV_T + logf(rs);
        g_rowval[row] = lse - d * INV_T;
    }
}

// ---------------------------------------------------------------------------
// Kernel D: deterministic final reduction (1024 threads)
// ---------------------------------------------------------------------------
__global__ void finalize_kernel(float* __restrict__ out) {
    __shared__ float sm[32];
    int tdx = threadIdx.x;
    float s = 0.f;
#pragma unroll
    for (int i = 0; i < 8; i++) s += g_rowval[tdx + i * 1024];
#pragma unroll
    for (int o = 16; o; o >>= 1) s += __shfl_xor_sync(0xffffffffu, s, o);
    if ((tdx & 31) == 0) sm[tdx >> 5] = s;
    __syncthreads();
    if (tdx < 32) {
        float v = sm[tdx];
#pragma unroll
        for (int o = 16; o; o >>= 1) v += __shfl_xor_sync(0xffffffffu, v, o);
        if (tdx == 0) out[0] = v / (float)BROWS;
    }
}

// ---------------------------------------------------------------------------
extern "C" void kernel_launch(void* const* d_in, const int* in_sizes, int n_in,
                              void* d_out, int out_size) {
    const float* feat   = (const float*)d_in[0];
    const int*   ids    = (const int*)d_in[1];
    const int*   anchor = (const int*)d_in[2];
    float*       out    = (float*)d_out;

    cudaFuncSetAttribute(gemm_lse_mma,
                         cudaFuncAttributeMaxDynamicSharedMemorySize, SMEM_BYTES);

    dim3 b32x8(32, 8);
    normalize_kernel<<<BROWS / 8, b32x8>>>(feat);

    gemm_lse_mma<<<GRIDSZ, 256, SMEM_BYTES>>>();

    pick_kernel<<<BROWS / 8, b32x8>>>(ids, anchor);
    finalize_kernel<<<1, 1024>>>(out);
}

// round 11
// speedup vs baseline: 1.3465x; 1.3465x over previous
#include <cuda_runtime.h>
#include <cuda_bf16.h>
#include <cstdint>
#include <math.h>

// Problem constants
#define BROWS 8192
#define DIM   512
#define INV_T 14.285714285714286f   // 1/0.07

// Tiling: CTA 128x128 = 4 warps x (64x64), mma m16n8k16 bf16
#define TM 128
#define TN 128
#define KC 64                        // bf16 elements per chunk (128B rows)
#define NCHUNK (DIM / KC)            // 8
#define NB (BROWS / TM)              // 64 blocks per dim
#define NTILES (NB * (NB + 1) / 2)   // 2080 lower-tri tiles
#define NTHREADS 128

#define TILE_BYTES  (128 * 128)      // one 128-row x 128B tile (16 KB)
#define STAGE_BYTES (2 * TILE_BYTES) // A + B (32 KB)
#define STAGES 3
#define SMEM_BYTES  (STAGES * STAGE_BYTES)   // 96 KB

#define SWZ(o) ((o) ^ (((o) >> 3) & 0x70))

// Scratch (static device globals — no allocation)
__device__ __nv_bfloat16 g_f[BROWS * DIM];   // bf16 normalized features (8 MB)
__device__ float g_partial[NB][BROWS];       // per-block exp row sums
__device__ float g_rowval[BROWS];

// ---------------------------------------------------------------------------
__device__ __forceinline__ uint32_t smem_u32(const void* p) {
    uint32_t a;
    asm("{ .reg .u64 t; cvta.to.shared.u64 t, %1; cvt.u32.u64 %0, t; }"
        : "=r"(a) : "l"(p));
    return a;
}
__device__ __forceinline__ void cp16(uint32_t dst, const void* src) {
    asm volatile("cp.async.cg.shared.global [%0], [%1], 16;"
                 :: "r"(dst), "l"(src) : "memory");
}
__device__ __forceinline__ void ldsm_x4(uint32_t* r, uint32_t addr) {
    asm volatile("ldmatrix.sync.aligned.m8n8.x4.shared.b16 {%0,%1,%2,%3}, [%4];"
                 : "=r"(r[0]), "=r"(r[1]), "=r"(r[2]), "=r"(r[3]) : "r"(addr));
}
__device__ __forceinline__ void mma_bf16(float* c, const uint32_t* a,
                                         uint32_t b0, uint32_t b1) {
    asm volatile(
        "mma.sync.aligned.m16n8k16.row.col.f32.bf16.bf16.f32 "
        "{%0,%1,%2,%3}, {%4,%5,%6,%7}, {%8,%9}, {%0,%1,%2,%3};"
        : "+f"(c[0]), "+f"(c[1]), "+f"(c[2]), "+f"(c[3])
        : "r"(a[0]), "r"(a[1]), "r"(a[2]), "r"(a[3]), "r"(b0), "r"(b1));
}

// ---------------------------------------------------------------------------
// Kernel A: row L2-normalize + round to bf16
// ---------------------------------------------------------------------------
__global__ void normalize_kernel(const float* __restrict__ x) {
    int row  = blockIdx.x * 8 + threadIdx.y;
    int lane = threadIdx.x;
    const float* xr = x + (size_t)row * DIM;
    float v[16];
    float s = 0.f;
#pragma unroll
    for (int i = 0; i < 16; i++) { v[i] = xr[lane + i * 32]; s += v[i] * v[i]; }
#pragma unroll
    for (int o = 16; o; o >>= 1) s += __shfl_xor_sync(0xffffffffu, s, o);
    float inv = 1.0f / fmaxf(sqrtf(s), 1e-12f);
    __nv_bfloat16* fr = g_f + (size_t)row * DIM;
#pragma unroll
    for (int i = 0; i < 16; i++)
        fr[lane + i * 32] = __float2bfloat16_rn(v[i] * inv);
}

// ---------------------------------------------------------------------------
// Kernel B: bf16 mma.sync GEMM, lower-tri tiles, cp.async 3-stage pipeline.
// 4 warps of 64x64 (2x2 warp grid): 33% less LDSM traffic per MAC than 32x64.
// Schedule = R6 (fastest measured): issue(c+2) -> wait(1) -> sync -> compute
// -> sync.
// ---------------------------------------------------------------------------
extern __shared__ char dynsm[];

__global__ __launch_bounds__(NTHREADS, 2) void gemm_lse_mma() {
    __shared__ float red_r[TM][2];
    __shared__ float red_c[TN][2];

    const int tid  = threadIdx.x;
    const int wid  = tid >> 5;
    const int lane = tid & 31;
    const int wr   = wid & 1;        // warp row (M chunks of 64)
    const int wc   = wid >> 1;       // warp col (N chunks of 64)
    const int g    = lane >> 2;
    const int t    = lane & 3;

    // decode lower-tri pair (bi >= bj)
    int idx = blockIdx.x;
    int bi = (int)((sqrtf(8.0f * (float)idx + 1.0f) - 1.0f) * 0.5f);
    while ((bi + 1) * (bi + 2) / 2 <= idx) bi++;
    while (bi * (bi + 1) / 2 > idx) bi--;
    int bj = idx - bi * (bi + 1) / 2;
    const int r0 = bi * TM;
    const int j0 = bj * TN;
    const bool offdiag = (bi != bj);

    const __nv_bfloat16* srcA = g_f + (size_t)r0 * DIM;
    const __nv_bfloat16* srcB = g_f + (size_t)j0 * DIM;

    const uint32_t smem_base = smem_u32(dynsm);

    const int srow = tid >> 3;       // 0..15; +16 per iter (8 iters = 128 rows)
    const int sseg = tid & 7;

    const int a_row  = wr * 64 + (lane & 15);
    const int a_koff = (lane >> 4) * 16;
    const int b_row  = wc * 64 + (lane & 7) + ((lane >> 4) << 3);
    const int b_koff = ((lane >> 3) & 1) * 16;

    float acc[4][8][4];
#pragma unroll
    for (int mt = 0; mt < 4; mt++)
#pragma unroll
        for (int nt = 0; nt < 8; nt++)
#pragma unroll
            for (int rr = 0; rr < 4; rr++) acc[mt][nt][rr] = 0.f;

    auto issue_chunk = [&](int c, int s) {
        const uint32_t sa = smem_base + s * STAGE_BYTES;
        const int ko = c * KC;
#pragma unroll
        for (int it = 0; it < 8; it++) {
            int row = srow + it * 16;
            uint32_t off = SWZ(row * 128 + sseg * 16);
            cp16(sa + off, srcA + (size_t)row * DIM + ko + sseg * 8);
            cp16(sa + TILE_BYTES + off, srcB + (size_t)row * DIM + ko + sseg * 8);
        }
        asm volatile("cp.async.commit_group;" ::: "memory");
    };

    // prologue: stages 0..STAGES-2
#pragma unroll
    for (int s = 0; s < STAGES - 1; s++) issue_chunk(s, s);

    for (int c = 0; c < NCHUNK; c++) {
        if (c + STAGES - 1 < NCHUNK) {
            issue_chunk(c + STAGES - 1, (c + STAGES - 1) % STAGES);
            asm volatile("cp.async.wait_group %0;" :: "n"(STAGES - 2) : "memory");
        } else {
            asm volatile("cp.async.wait_group 0;" ::: "memory");
        }
        __syncthreads();

        const uint32_t sa = smem_base + (c % STAGES) * STAGE_BYTES;
        const uint32_t sb = sa + TILE_BYTES;

#pragma unroll
        for (int kstep = 0; kstep < 4; kstep++) {
            uint32_t afr[4][4];
#pragma unroll
            for (int mt = 0; mt < 4; mt++) {
                int off = SWZ((a_row + mt * 16) * 128 + kstep * 32 + a_koff);
                ldsm_x4(afr[mt], sa + off);
            }
            uint32_t bfr[8][2];
#pragma unroll
            for (int p = 0; p < 4; p++) {
                uint32_t r[4];
                int off = SWZ((b_row + p * 16) * 128 + kstep * 32 + b_koff);
                ldsm_x4(r, sb + off);
                bfr[2 * p][0] = r[0]; bfr[2 * p][1] = r[1];
                bfr[2 * p + 1][0] = r[2]; bfr[2 * p + 1][1] = r[3];
            }
#pragma unroll
            for (int mt = 0; mt < 4; mt++)
#pragma unroll
                for (int nt = 0; nt < 8; nt++)
                    mma_bf16(acc[mt][nt], afr[mt], bfr[nt][0], bfr[nt][1]);
        }
        __syncthreads();   // all reads of this stage done before reuse
    }

    // ---- epilogue: exp in place; row sums + col sums (off-diag) ----
#pragma unroll
    for (int mt = 0; mt < 4; mt++)
#pragma unroll
        for (int nt = 0; nt < 8; nt++)
#pragma unroll
            for (int rr = 0; rr < 4; rr++)
                acc[mt][nt][rr] = __expf((acc[mt][nt][rr] - 1.0f) * INV_T);

    // row sums: row = wr*64 + mt*16 + hi*8 + g, reduce over t (lanes ^1,^2)
#pragma unroll
    for (int mt = 0; mt < 4; mt++)
#pragma unroll
        for (int hi = 0; hi < 2; hi++) {
            float s = 0.f;
#pragma unroll
            for (int nt = 0; nt < 8; nt++)
                s += acc[mt][nt][hi * 2 + 0] + acc[mt][nt][hi * 2 + 1];
            s += __shfl_xor_sync(0xffffffffu, s, 1);
            s += __shfl_xor_sync(0xffffffffu, s, 2);
            if (t == 0) red_r[wr * 64 + mt * 16 + hi * 8 + g][wc] = s;
        }

    // col sums: col = wc*64 + nt*8 + t*2 + {0,1}; sum over mt, reduce over g
    if (offdiag) {
#pragma unroll
        for (int nt = 0; nt < 8; nt++) {
            float cs0 = 0.f, cs1 = 0.f;
#pragma unroll
            for (int mt = 0; mt < 4; mt++) {
                cs0 += acc[mt][nt][0] + acc[mt][nt][2];
                cs1 += acc[mt][nt][1] + acc[mt][nt][3];
            }
#pragma unroll
            for (int o = 4; o <= 16; o <<= 1) {
                cs0 += __shfl_xor_sync(0xffffffffu, cs0, o);
                cs1 += __shfl_xor_sync(0xffffffffu, cs1, o);
            }
            if (g == 0) {
                red_c[wc * 64 + nt * 8 + t * 2 + 0][wr] = cs0;
                red_c[wc * 64 + nt * 8 + t * 2 + 1][wr] = cs1;
            }
        }
    }
    __syncthreads();

    // 128 threads, one row each
    g_partial[bj][r0 + tid] = red_r[tid][0] + red_r[tid][1];
    if (offdiag)
        g_partial[bi][j0 + tid] = red_c[tid][0] + red_c[tid][1];
}

// ---------------------------------------------------------------------------
// Kernel C: labels (col 0/1), picked dot (bf16 inputs, fp32 accum), lse
// ---------------------------------------------------------------------------
__global__ void pick_kernel(const int* __restrict__ ids,
                            const int* __restrict__ anchor) {
    int row  = blockIdx.x * 8 + threadIdx.y;
    int lane = threadIdx.x;

    int aid       = ids[anchor[0]];
    int same_last = (ids[BROWS - 1] == aid);
    int label;
    if (row == BROWS - 1)
        label = (same_last && (ids[BROWS - 2] == aid)) ? 1 : 0;
    else
        label = ((ids[row] == aid) && same_last) ? 1 : 0;

    const __nv_bfloat16* fi = g_f + (size_t)row * DIM;
    const __nv_bfloat16* fc = g_f + (size_t)label * DIM;
    float d = 0.f;
#pragma unroll
    for (int i = 0; i < 16; i++)
        d = fmaf(__bfloat162float(fi[lane + i * 32]),
                 __bfloat162float(fc[lane + i * 32]), d);

    // parallel partial-slot sum: lanes each grab 2 of the 64 slots
    float rs = g_partial[lane][row] + g_partial[lane + 32][row];

#pragma unroll
    for (int o = 16; o; o >>= 1) {
        d  += __shfl_xor_sync(0xffffffffu, d, o);
        rs += __shfl_xor_sync(0xffffffffu, rs, o);
    }

    if (lane == 0) {
        float lse = INV_T + logf(rs);
        g_rowval[row] = lse - d * INV_T;
    }
}

// ---------------------------------------------------------------------------
// Kernel D: deterministic final reduction (1024 threads)
// ---------------------------------------------------------------------------
__global__ void finalize_kernel(float* __restrict__ out) {
    __shared__ float sm[32];
    int tdx = threadIdx.x;
    float s = 0.f;
#pragma unroll
    for (int i = 0; i < 8; i++) s += g_rowval[tdx + i * 1024];
#pragma unroll
    for (int o = 16; o; o >>= 1) s += __shfl_xor_sync(0xffffffffu, s, o);
    if ((tdx & 31) == 0) sm[tdx >> 5] = s;
    __syncthreads();
    if (tdx < 32) {
        float v = sm[tdx];
#pragma unroll
        for (int o = 16; o; o >>= 1) v += __shfl_xor_sync(0xffffffffu, v, o);
        if (tdx == 0) out[0] = v / (float)BROWS;
    }
}

// ---------------------------------------------------------------------------
extern "C" void kernel_launch(void* const* d_in, const int* in_sizes, int n_in,
                              void* d_out, int out_size) {
    const float* feat   = (const float*)d_in[0];
    const int*   ids    = (const int*)d_in[1];
    const int*   anchor = (const int*)d_in[2];
    float*       out    = (float*)d_out;

    cudaFuncSetAttribute(gemm_lse_mma,
                         cudaFuncAttributeMaxDynamicSharedMemorySize, SMEM_BYTES);

    dim3 b32x8(32, 8);
    normalize_kernel<<<BROWS / 8, b32x8>>>(feat);

    gemm_lse_mma<<<NTILES, NTHREADS, SMEM_BYTES>>>();

    pick_kernel<<<BROWS / 8, b32x8>>>(ids, anchor);
    finalize_kernel<<<1, 1024>>>(out);
}